// round 15
// baseline (speedup 1.0000x reference)
#include <cuda_runtime.h>
#include <cuda_bf16.h>
#include <cstdint>

#define B_ 16
#define T_ 2048
#define L_ 128
#define H_ 512
#define HH (H_ * H_)
#define M_IN 256
#define F_ 1024
#define LP 130                 // U table row-block: 128 ch + 1 const + 1 pad
#define C_CHUNK 16
#define KX 2048                // X k-width (no const row)
#define MZ 256                 // 16 q * 16 batch
#define NSPLIT 8
#define KPER 256
#define GRID 288               // persistent blocks, 2/SM co-resident (<=296)
#define NPOW 7                 // A^2,A^4,A^8,A^16,A^32,A^64,A^128

typedef __nv_bfloat16 bf16;

__device__ __align__(16) bf16 g_A0h[HH], g_A0l[HH];
__device__ __align__(16) bf16 g_Uh[C_CHUNK * LP * H_], g_Ul[C_CHUNK * LP * H_];
__device__ __align__(16) bf16 g_Ph[NPOW * HH], g_Pl[NPOW * HH];
__device__ __align__(16) bf16 g_Xh[MZ * KX], g_Xl[MZ * KX];
__device__ __align__(16) float g_Zp[NSPLIT * MZ * H_];
__device__ __align__(16) float g_Zf[MZ * H_];
__device__ __align__(16) bf16 g_Zh[MZ * H_], g_Zl[MZ * H_];
__device__ __align__(16) float g_Waf[128 * H_];
__device__ __align__(16) bf16 g_Wah[128 * H_], g_Wal[128 * H_];
__device__ __align__(16) float g_Wbf[128 * H_];
__device__ __align__(16) bf16 g_Wbh[128 * H_], g_Wbl[128 * H_];
__device__ __align__(16) float g_bias[H_];
__device__ int g_cnt;
__device__ int g_gen;

__device__ __forceinline__ void splitw(float v, bf16* ph, bf16* pl) {
    bf16 h = __float2bfloat16(v);
    *ph = h;
    *pl = __float2bfloat16(v - __bfloat162float(h));
}

// ------------------------- prep: splitA + initW0 + bar reset ---------------
__global__ void k_prep(const float* __restrict__ A, const float* __restrict__ We,
                       const float* __restrict__ be, const float* __restrict__ Wb) {
    const int NB_A = HH / 256;   // 1024
    int bid = blockIdx.x, tid = threadIdx.x;
    if (bid == 0 && tid == 0) { g_cnt = 0; g_gen = 0; }
    if (bid < NB_A) {
        int i = bid * 256 + tid;
        splitw(A[i], &g_A0h[i], &g_A0l[i]);
    } else {
        int i = (bid - NB_A) * 256 + tid;
        if (i >= LP * H_) return;
        int l = i >> 9, h = i & 511;
        float acc = 0.f;
        if (l < 128) { for (int m = 0; m < M_IN; m++) acc += We[l * M_IN + m] * Wb[m * H_ + h]; }
        else if (l == 128) { for (int m = 0; m < M_IN; m++) acc += be[m] * Wb[m * H_ + h]; }
        splitw(acc, &g_Uh[i], &g_Ul[i]);
    }
}

// ---------------------------------------------------------------------------
__device__ __forceinline__ void ldsm4(uint32_t* r, const void* p) {
    uint32_t addr = (uint32_t)__cvta_generic_to_shared(p);
    asm volatile("ldmatrix.sync.aligned.m8n8.x4.shared.b16 {%0,%1,%2,%3}, [%4];"
                 : "=r"(r[0]), "=r"(r[1]), "=r"(r[2]), "=r"(r[3]) : "r"(addr));
}
__device__ __forceinline__ void ldsm4t(uint32_t* r, const void* p) {
    uint32_t addr = (uint32_t)__cvta_generic_to_shared(p);
    asm volatile("ldmatrix.sync.aligned.m8n8.x4.trans.shared.b16 {%0,%1,%2,%3}, [%4];"
                 : "=r"(r[0]), "=r"(r[1]), "=r"(r[2]), "=r"(r[3]) : "r"(addr));
}
__device__ __forceinline__ void mma16816(float* d, const uint32_t* a, const uint32_t* b) {
    asm volatile("mma.sync.aligned.m16n8k16.row.col.f32.bf16.bf16.f32 "
                 "{%0,%1,%2,%3}, {%4,%5,%6,%7}, {%8,%9}, {%0,%1,%2,%3};"
                 : "+f"(d[0]), "+f"(d[1]), "+f"(d[2]), "+f"(d[3])
                 : "r"(a[0]), "r"(a[1]), "r"(a[2]), "r"(a[3]), "r"(b[0]), "r"(b[1]));
}

// grid-wide barrier (all GRID blocks must be resident)
__device__ __forceinline__ void gbar(int& epoch) {
    __syncthreads();
    __threadfence();
    if (threadIdx.x == 0) {
        int t = atomicAdd(&g_cnt, 1);
        if (t == GRID - 1) {
            atomicExch(&g_cnt, 0);
            __threadfence();
            atomicAdd(&g_gen, 1);
        }
        while (*(volatile int*)&g_gen < epoch + 1) {}
    }
    __syncthreads();
    epoch++;
}

#define SMEM_BYTES 38912

// shared 64x64xK=512 double-buffered split-bf16 mma mainloop.
// aH/aL: per-thread A row src (+ac8 offset applied), nullptr = zero rows.
// bH/bL: per-thread B src = base + sbk*H_ + col0 + sbn (row-major [k][n]).
__device__ __forceinline__ void core512(
    const bf16* __restrict__ aH, const bf16* __restrict__ aL,
    const bf16* __restrict__ bH, const bf16* __restrict__ bL,
    float acc[2][2][4], char* sm)
{
    bf16* ash = (bf16*)sm;
    bf16* asl = ash + 5120;
    bf16* bsh = asl + 5120;
    bf16* bsl = bsh + 4608;
    int tid = threadIdx.x;
    int lane = tid & 31, wid = tid >> 5;
    int wm = wid & 1, wn = wid >> 1;
    int a_r = (lane & 7) + (lane & 8);
    int a_c = (lane & 16) ? 8 : 0;
    int am = tid >> 2, ac8 = (tid & 3) * 8;
    int sbk = tid >> 3, sbn = (tid & 7) * 8;

    uint4 pAh = make_uint4(0, 0, 0, 0), pAl = pAh, pBh, pBl;
    if (aH) { pAh = *(const uint4*)aH; pAl = *(const uint4*)aL; }
    pBh = *(const uint4*)bH;
    pBl = *(const uint4*)bL;

    int st = 0;
    #pragma unroll 1
    for (int it = 0; it < 16; it++) {
        *(uint4*)&ash[st * 2560 + am * 40 + ac8] = pAh;
        *(uint4*)&asl[st * 2560 + am * 40 + ac8] = pAl;
        *(uint4*)&bsh[st * 2304 + sbk * 72 + sbn] = pBh;
        *(uint4*)&bsl[st * 2304 + sbk * 72 + sbn] = pBl;
        __syncthreads();

        if (it + 1 < 16) {
            int kn = (it + 1) << 5;
            if (aH) { pAh = *(const uint4*)(aH + kn); pAl = *(const uint4*)(aL + kn); }
            pBh = *(const uint4*)(bH + (size_t)kn * H_);
            pBl = *(const uint4*)(bL + (size_t)kn * H_);
        }

        #pragma unroll
        for (int ks = 0; ks < 2; ks++) {
            int kc = ks * 16;
            uint32_t ah[2][4], al[2][4], bh[4], bl[4];
            #pragma unroll
            for (int mt = 0; mt < 2; mt++) {
                int mr = wm * 32 + mt * 16 + a_r;
                ldsm4(ah[mt], &ash[st * 2560 + mr * 40 + kc + a_c]);
                ldsm4(al[mt], &asl[st * 2560 + mr * 40 + kc + a_c]);
            }
            {
                int nb = wn * 16 + a_c;
                ldsm4t(bh, &bsh[st * 2304 + (kc + a_r) * 72 + nb]);
                ldsm4t(bl, &bsl[st * 2304 + (kc + a_r) * 72 + nb]);
            }
            #pragma unroll
            for (int mt = 0; mt < 2; mt++)
                #pragma unroll
                for (int nt = 0; nt < 2; nt++) {
                    const uint32_t* bhf = &bh[nt * 2];
                    const uint32_t* blf = &bl[nt * 2];
                    mma16816(acc[mt][nt], ah[mt], bhf);
                    mma16816(acc[mt][nt], ah[mt], blf);
                    mma16816(acc[mt][nt], al[mt], bhf);
                }
        }
        st ^= 1;
    }
    __syncthreads();   // protect smem before next tile reuses it
}

// stage tile: C = [U(:Mu) ; A2] @ A2; outputs hi/lo split rows
__device__ void tg_tile(const bf16* __restrict__ A2h, const bf16* __restrict__ A2l,
                        int Mu, int Mtot,
                        bf16* C1h, bf16* C1l, bf16* C2h, bf16* C2l,
                        int tile, char* sm)
{
    int tid = threadIdx.x;
    int lane = tid & 31, wid = tid >> 5;
    int wm = wid & 1, wn = wid >> 1;
    int row0 = (tile >> 3) * 64, col0 = (tile & 7) * 64;
    int am = tid >> 2, ac8 = (tid & 3) * 8;
    int sbk = tid >> 3, sbn = (tid & 7) * 8;

    int ar_g = row0 + am;
    bool a_ok = (ar_g < Mtot);
    bool a_lo = a_ok && (ar_g < Mu);
    const bf16* aH = a_ok ? ((a_lo ? g_Uh : A2h) + (size_t)(a_lo ? ar_g : ar_g - Mu) * H_ + ac8) : nullptr;
    const bf16* aL = a_ok ? ((a_lo ? g_Ul : A2l) + (size_t)(a_lo ? ar_g : ar_g - Mu) * H_ + ac8) : nullptr;
    const bf16* bH = A2h + (size_t)sbk * H_ + col0 + sbn;
    const bf16* bL = A2l + (size_t)sbk * H_ + col0 + sbn;

    float acc[2][2][4] = {};
    core512(aH, aL, bH, bL, acc, sm);

    #pragma unroll
    for (int mt = 0; mt < 2; mt++)
        #pragma unroll
        for (int nt = 0; nt < 2; nt++) {
            int c = col0 + wn * 16 + nt * 8 + (lane & 3) * 2;
            #pragma unroll
            for (int half = 0; half < 2; half++) {
                int r = row0 + wm * 32 + mt * 16 + (lane >> 2) + half * 8;
                if (r >= Mtot) continue;
                float v0 = acc[mt][nt][half * 2], v1 = acc[mt][nt][half * 2 + 1];
                bool lo = (r < Mu);
                size_t ro = lo ? (size_t)r * H_ : (size_t)(r - Mu) * H_;
                bf16* ch = lo ? C1h : C2h;
                bf16* cl = lo ? C1l : C2l;
                splitw(v0, &ch[ro + c], &cl[ro + c]);
                splitw(v1, &ch[ro + c + 1], &cl[ro + c + 1]);
            }
        }
}

// squaring tile: Gout = Gin @ Gin (64 tiles, M=512)
__device__ void sq_tile(const bf16* __restrict__ Gh, const bf16* __restrict__ Gl,
                        bf16* OutH, bf16* OutL, int tile, char* sm)
{
    int tid = threadIdx.x;
    int lane = tid & 31, wid = tid >> 5;
    int wm = wid & 1, wn = wid >> 1;
    int row0 = (tile >> 3) * 64, col0 = (tile & 7) * 64;
    int am = tid >> 2, ac8 = (tid & 3) * 8;
    int sbk = tid >> 3, sbn = (tid & 7) * 8;

    const bf16* aH = Gh + (size_t)(row0 + am) * H_ + ac8;
    const bf16* aL = Gl + (size_t)(row0 + am) * H_ + ac8;
    const bf16* bH = Gh + (size_t)sbk * H_ + col0 + sbn;
    const bf16* bL = Gl + (size_t)sbk * H_ + col0 + sbn;

    float acc[2][2][4] = {};
    core512(aH, aL, bH, bL, acc, sm);

    #pragma unroll
    for (int mt = 0; mt < 2; mt++)
        #pragma unroll
        for (int nt = 0; nt < 2; nt++) {
            int c = col0 + wn * 16 + nt * 8 + (lane & 3) * 2;
            #pragma unroll
            for (int half = 0; half < 2; half++) {
                int r = row0 + wm * 32 + mt * 16 + (lane >> 2) + half * 8;
                size_t ro = (size_t)r * H_;
                splitw(acc[mt][nt][half * 2],     &OutH[ro + c],     &OutL[ro + c]);
                splitw(acc[mt][nt][half * 2 + 1], &OutH[ro + c + 1], &OutL[ro + c + 1]);
            }
        }
}

// combine tile: out_j = in_{2j} + in_{2j+1} @ G   (stacked: out row m=j*16+b)
// odd in-row = 32j+16+b, even in-row = 32j+b. Mout = #out rows.
__device__ void cb_tile(const float* __restrict__ inF,
                        const bf16* __restrict__ inH, const bf16* __restrict__ inL,
                        const bf16* __restrict__ Gh, const bf16* __restrict__ Gl,
                        float* outF, bf16* outH, bf16* outL,
                        int Mout, int tile, char* sm)
{
    int tid = threadIdx.x;
    int lane = tid & 31, wid = tid >> 5;
    int wm = wid & 1, wn = wid >> 1;
    int row0 = (tile >> 3) * 64, col0 = (tile & 7) * 64;
    int am = tid >> 2, ac8 = (tid & 3) * 8;
    int sbk = tid >> 3, sbn = (tid & 7) * 8;

    int m = row0 + am;
    bool ok = (m < Mout);
    int arow = 32 * (m >> 4) + 16 + (m & 15);
    const bf16* aH = ok ? inH + (size_t)arow * H_ + ac8 : nullptr;
    const bf16* aL = ok ? inL + (size_t)arow * H_ + ac8 : nullptr;
    const bf16* bH = Gh + (size_t)sbk * H_ + col0 + sbn;
    const bf16* bL = Gl + (size_t)sbk * H_ + col0 + sbn;

    float acc[2][2][4] = {};
    core512(aH, aL, bH, bL, acc, sm);

    #pragma unroll
    for (int mt = 0; mt < 2; mt++)
        #pragma unroll
        for (int nt = 0; nt < 2; nt++) {
            int c = col0 + wn * 16 + nt * 8 + (lane & 3) * 2;
            #pragma unroll
            for (int half = 0; half < 2; half++) {
                int r = row0 + wm * 32 + mt * 16 + (lane >> 2) + half * 8;
                if (r >= Mout) continue;
                int ev = 32 * (r >> 4) + (r & 15);
                float v0 = acc[mt][nt][half * 2]     + inF[(size_t)ev * H_ + c];
                float v1 = acc[mt][nt][half * 2 + 1] + inF[(size_t)ev * H_ + c + 1];
                size_t ro = (size_t)r * H_;
                outF[ro + c] = v0;
                outF[ro + c + 1] = v1;
                splitw(v0, &outH[ro + c], &outL[ro + c]);
                splitw(v1, &outH[ro + c + 1], &outL[ro + c + 1]);
            }
        }
}

// zgemm tile: Zp[bz] = X @ U' (U' row k = U row (k>>7)*130+(k&127)), K-slice
__device__ void z_tile(int tile, char* sm) {
    bf16* ash = (bf16*)sm;
    bf16* asl = ash + 5120;
    bf16* bsh = asl + 5120;
    bf16* bsl = bsh + 4608;

    int tid = threadIdx.x;
    int lane = tid & 31, wid = tid >> 5;
    int wm = wid & 1, wn = wid >> 1;
    int bx = tile & 7, by = (tile >> 3) & 3, bz = tile >> 5;
    int row0 = by * 64, col0 = bx * 64;
    int k0 = bz * KPER;
    size_t coff = (size_t)bz * MZ * H_;

    float acc[2][2][4] = {};
    int a_r = (lane & 7) + (lane & 8);
    int a_c = (lane & 16) ? 8 : 0;
    int am = tid >> 2, ac8 = (tid & 3) * 8;
    int sbk = tid >> 3, sbn = (tid & 7) * 8;

    const bf16* ash_src = g_Xh + (size_t)(row0 + am) * KX + ac8;
    const bf16* asl_src = g_Xl + (size_t)(row0 + am) * KX + ac8;

    uint4 pAh, pAl, pBh, pBl;
    {
        pAh = *(const uint4*)(ash_src + k0);
        pAl = *(const uint4*)(asl_src + k0);
        int kg = k0 + sbk;
        size_t brow = (size_t)((kg >> 7) * LP + (kg & 127)) * H_ + col0 + sbn;
        pBh = *(const uint4*)(g_Uh + brow);
        pBl = *(const uint4*)(g_Ul + brow);
    }

    int st = 0;
    #pragma unroll 1
    for (int it = 0; it < (KPER >> 5); it++) {
        *(uint4*)&ash[st * 2560 + am * 40 + ac8] = pAh;
        *(uint4*)&asl[st * 2560 + am * 40 + ac8] = pAl;
        *(uint4*)&bsh[st * 2304 + sbk * 72 + sbn] = pBh;
        *(uint4*)&bsl[st * 2304 + sbk * 72 + sbn] = pBl;
        __syncthreads();

        if (it + 1 < (KPER >> 5)) {
            int kn = k0 + ((it + 1) << 5);
            pAh = *(const uint4*)(ash_src + kn);
            pAl = *(const uint4*)(asl_src + kn);
            int kg = kn + sbk;
            size_t brow = (size_t)((kg >> 7) * LP + (kg & 127)) * H_ + col0 + sbn;
            pBh = *(const uint4*)(g_Uh + brow);
            pBl = *(const uint4*)(g_Ul + brow);
        }

        #pragma unroll
        for (int ks = 0; ks < 2; ks++) {
            int kc = ks * 16;
            uint32_t ah[2][4], al[2][4], bh[4], bl[4];
            #pragma unroll
            for (int mt = 0; mt < 2; mt++) {
                int mr = wm * 32 + mt * 16 + a_r;
                ldsm4(ah[mt], &ash[st * 2560 + mr * 40 + kc + a_c]);
                ldsm4(al[mt], &asl[st * 2560 + mr * 40 + kc + a_c]);
            }
            {
                int nb = wn * 16 + a_c;
                ldsm4t(bh, &bsh[st * 2304 + (kc + a_r) * 72 + nb]);
                ldsm4t(bl, &bsl[st * 2304 + (kc + a_r) * 72 + nb]);
            }
            #pragma unroll
            for (int mt = 0; mt < 2; mt++)
                #pragma unroll
                for (int nt = 0; nt < 2; nt++) {
                    const uint32_t* bhf = &bh[nt * 2];
                    const uint32_t* blf = &bl[nt * 2];
                    mma16816(acc[mt][nt], ah[mt], bhf);
                    mma16816(acc[mt][nt], ah[mt], blf);
                    mma16816(acc[mt][nt], al[mt], bhf);
                }
        }
        st ^= 1;
    }
    __syncthreads();

    #pragma unroll
    for (int mt = 0; mt < 2; mt++)
        #pragma unroll
        for (int nt = 0; nt < 2; nt++) {
            int c = col0 + wn * 16 + nt * 8 + (lane & 3) * 2;
            #pragma unroll
            for (int half = 0; half < 2; half++) {
                int r = row0 + wm * 32 + mt * 16 + (lane >> 2) + half * 8;
                float* cp = g_Zp + coff + (size_t)r * H_ + c;
                cp[0] = acc[mt][nt][half * 2];
                cp[1] = acc[mt][nt][half * 2 + 1];
            }
        }
}

// ------------------------------- mega kernel -------------------------------
__global__ __launch_bounds__(256, 2) void k_mega(
    const float* __restrict__ x,
    const float* __restrict__ Wr, const float* __restrict__ br,
    const float* __restrict__ lng, const float* __restrict__ lnb,
    const float* __restrict__ W1, const float* __restrict__ b1,
    const float* __restrict__ W2, const float* __restrict__ b2,
    float* __restrict__ out)
{
    __shared__ __align__(16) char sm[SMEM_BYTES];
    int bid = blockIdx.x, tid = threadIdx.x;
    int epoch = 0;

    bf16* P3h = g_Ph + 3 * (size_t)HH; bf16* P3l = g_Pl + 3 * (size_t)HH;  // A^16
    bf16* P4h = g_Ph + 4 * (size_t)HH; bf16* P4l = g_Pl + 4 * (size_t)HH;  // A^32
    bf16* P5h = g_Ph + 5 * (size_t)HH; bf16* P5l = g_Pl + 5 * (size_t)HH;  // A^64
    bf16* P6h = g_Ph + 6 * (size_t)HH; bf16* P6l = g_Pl + 6 * (size_t)HH;  // A^128

    // ---- phase 0: gather X + stage 0..3 (4 gbars) ----
    for (int i = bid * 256 + tid; i < MZ * KX; i += GRID * 256) {
        int m = i >> 11, kk = i & 2047;
        int r = kk >> 7, l = kk & 127;
        int q = m >> 4, b = m & 15;
        float v = x[((size_t)b * T_ + (T_ - 1) - (q * C_CHUNK + r)) * L_ + l];
        splitw(v, &g_Xh[i], &g_Xl[i]);
    }
    {
        const int MuT[4] = {130, 260, 520, 1040};
        const int NTT[4] = {88, 104, 136, 200};
        for (int s = 0; s < 4; s++) {
            const bf16* A2h = s ? g_Ph + (size_t)(s - 1) * HH : g_A0h;
            const bf16* A2l = s ? g_Pl + (size_t)(s - 1) * HH : g_A0l;
            int Mu = MuT[s];
            for (int t = bid; t < NTT[s]; t += GRID)
                tg_tile(A2h, A2l, Mu, Mu + H_,
                        g_Uh + (size_t)Mu * H_, g_Ul + (size_t)Mu * H_,
                        g_Ph + (size_t)s * HH, g_Pl + (size_t)s * HH, t, sm);
            gbar(epoch);
        }
    }

    // ---- phase Z: zgemm (256 tiles) + G1=A^32 squaring (64 tiles) + bias ----
    if (bid * 256 + tid < H_) {
        int h = bid * 256 + tid;
        float s = 0.f;
        #pragma unroll
        for (int r = 0; r < C_CHUNK; r++) {
            size_t off = (size_t)(r * LP + 128) * H_ + h;
            s += __bfloat162float(g_Uh[off]) + __bfloat162float(g_Ul[off]);
        }
        g_bias[h] = s;
    }
    for (int t = bid; t < 256 + 64; t += GRID) {
        if (t < 256) z_tile(t, sm);
        else sq_tile(P3h, P3l, P4h, P4l, t - 256, sm);
    }
    gbar(epoch);

    // ---- phase R: reduce Z (+bias, split) + G2=A^64 squaring ----
    for (int i = bid * 256 + tid; i < MZ * H_; i += GRID * 256) {
        float v = g_bias[i & 511];
        #pragma unroll
        for (int s = 0; s < NSPLIT; s++) v += g_Zp[(size_t)s * (MZ * H_) + i];
        g_Zf[i] = v;
        splitw(v, &g_Zh[i], &g_Zl[i]);
    }
    for (int t = bid; t < 64; t += GRID)
        sq_tile(P4h, P4l, P5h, P5l, t, sm);
    gbar(epoch);

    // ---- level 0: S = Z_even + Z_odd@A^16 (16 tiles) + G3=A^128 squaring ----
    for (int t = bid; t < 16 + 64; t += GRID) {
        if (t < 16) cb_tile(g_Zf, g_Zh, g_Zl, P3h, P3l, g_Waf, g_Wah, g_Wal, 128, t, sm);
        else sq_tile(P5h, P5l, P6h, P6l, t - 16, sm);
    }
    gbar(epoch);

    // ---- level 1: Wa(128) -> Wb(64) with A^32 ----
    for (int t = bid; t < 8; t += GRID)
        cb_tile(g_Waf, g_Wah, g_Wal, P4h, P4l, g_Wbf, g_Wbh, g_Wbl, 64, t, sm);
    gbar(epoch);

    // ---- level 2: Wb(64) -> Wa(32) with A^64 ----
    for (int t = bid; t < 8; t += GRID)
        cb_tile(g_Wbf, g_Wbh, g_Wbl, P5h, P5l, g_Waf, g_Wah, g_Wal, 32, t, sm);
    gbar(epoch);

    // ---- level 3: Wa(32) -> Wb(16) with A^128 : final h_T ----
    for (int t = bid; t < 8; t += GRID)
        cb_tile(g_Waf, g_Wah, g_Wal, P6h, P6l, g_Wbf, g_Wbh, g_Wbl, 16, t, sm);
    gbar(epoch);

    // ---- final: LN + MLP (bid < 16) ----
    if (bid < B_) {
        float* xs = (float*)sm;      // [128]
        float* z  = xs + 128;        // [512]
        float* a  = z + 512;         // [1024]
        float* r1 = a + 1024;        // [8]
        float* r2 = r1 + 8;          // [8]
        float* mus = r2 + 8;         // [2]
        int b = bid;
        if (tid < L_) xs[tid] = x[((size_t)b * T_ + (T_ - 1)) * L_ + tid];
        __syncthreads();
        for (int h = tid; h < H_; h += 256) {
            float acc = g_Wbf[b * H_ + h] + br[h];
            for (int l = 0; l < L_; l++) acc += xs[l] * Wr[(size_t)l * H_ + h];
            z[h] = acc;
        }
        __syncthreads();
        float s1 = 0.f, s2 = 0.f;
        for (int h = tid; h < H_; h += 256) { float v = z[h]; s1 += v; s2 += v * v; }
        #pragma unroll
        for (int o = 16; o; o >>= 1) {
            s1 += __shfl_xor_sync(0xFFFFFFFFu, s1, o);
            s2 += __shfl_xor_sync(0xFFFFFFFFu, s2, o);
        }
        if ((tid & 31) == 0) { r1[tid >> 5] = s1; r2[tid >> 5] = s2; }
        __syncthreads();
        if (tid == 0) {
            float t1 = 0.f, t2 = 0.f;
            #pragma unroll
            for (int i = 0; i < 8; i++) { t1 += r1[i]; t2 += r2[i]; }
            float mu = t1 / (float)H_;
            mus[0] = mu;
            mus[1] = rsqrtf(t2 / (float)H_ - mu * mu + 1e-5f);
        }
        __syncthreads();
        for (int h = tid; h < H_; h += 256) z[h] = (z[h] - mus[0]) * mus[1] * lng[h] + lnb[h];
        __syncthreads();
        for (int f = tid; f < F_; f += 256) {
            float acc = b1[f];
            for (int h = 0; h < H_; h++) acc += z[h] * W1[(size_t)h * F_ + f];
            a[f] = fmaxf(acc, 0.f);
        }
        __syncthreads();
        for (int h2 = tid; h2 < H_; h2 += 256) {
            float acc = b2[h2];
            for (int f = 0; f < F_; f++) acc += a[f] * W2[(size_t)f * H_ + h2];
            out[b * H_ + h2] = acc;
        }
    }
}

// ---------------------------------------------------------------------------
extern "C" void kernel_launch(void* const* d_in, const int* in_sizes, int n_in,
                              void* d_out, int out_size) {
    const float* x   = (const float*)d_in[0];
    const float* We  = (const float*)d_in[1];
    const float* be  = (const float*)d_in[2];
    const float* Wb  = (const float*)d_in[3];
    const float* A   = (const float*)d_in[4];
    const float* Wr  = (const float*)d_in[5];
    const float* br  = (const float*)d_in[6];
    const float* lng = (const float*)d_in[7];
    const float* lnb = (const float*)d_in[8];
    const float* W1  = (const float*)d_in[9];
    const float* b1  = (const float*)d_in[10];
    const float* W2  = (const float*)d_in[11];
    const float* b2  = (const float*)d_in[12];
    float* out = (float*)d_out;

    k_prep<<<1024 + 260, 256>>>(A, We, be, Wb);
    k_mega<<<GRID, 256>>>(x, Wr, br, lng, lnb, W1, b1, W2, b2, out);
}

// round 17
// speedup vs baseline: 1.0845x; 1.0845x over previous
#include <cuda_runtime.h>
#include <cuda_bf16.h>
#include <cstdint>

#define B_ 16
#define T_ 2048
#define L_ 128
#define H_ 512
#define HH (H_ * H_)
#define M_IN 256
#define F_ 1024
#define LP 130                 // U table row-block: 128 ch + 1 const + 1 pad
#define C_CHUNK 16
#define KX 2048                // X k-width (no const row)
#define MZ 256                 // 16 q * 16 batch
#define NSPLIT 8
#define KPER 256
#define GRID 288               // persistent blocks, 2/SM co-resident (<=296)
#define NPOW 7                 // A^2,A^4,A^8,A^16,A^32,A^64,A^128

// dynamic smem: 4 regions x double-buffer x 64rows x 72stride bf16
#define SMEM_BYTES 73728

typedef __nv_bfloat16 bf16;

__device__ __align__(16) bf16 g_A0h[HH], g_A0l[HH];
__device__ __align__(16) bf16 g_Uh[C_CHUNK * LP * H_], g_Ul[C_CHUNK * LP * H_];
__device__ __align__(16) bf16 g_Ph[NPOW * HH], g_Pl[NPOW * HH];
__device__ __align__(16) bf16 g_Xh[MZ * KX], g_Xl[MZ * KX];
__device__ __align__(16) float g_Zp[NSPLIT * MZ * H_];
__device__ __align__(16) float g_Zf[MZ * H_];
__device__ __align__(16) bf16 g_Zh[MZ * H_], g_Zl[MZ * H_];
__device__ __align__(16) float g_Waf[128 * H_];
__device__ __align__(16) bf16 g_Wah[128 * H_], g_Wal[128 * H_];
__device__ __align__(16) float g_Wbf[128 * H_];
__device__ __align__(16) bf16 g_Wbh[128 * H_], g_Wbl[128 * H_];
__device__ __align__(16) float g_bias[H_];
__device__ int g_cnt;
__device__ int g_gen;

__device__ __forceinline__ void splitw(float v, bf16* ph, bf16* pl) {
    bf16 h = __float2bfloat16(v);
    *ph = h;
    *pl = __float2bfloat16(v - __bfloat162float(h));
}

// ------------------------- prep: splitA + initW0 + bar reset ---------------
__global__ void k_prep(const float* __restrict__ A, const float* __restrict__ We,
                       const float* __restrict__ be, const float* __restrict__ Wb) {
    const int NB_A = HH / 256;   // 1024
    int bid = blockIdx.x, tid = threadIdx.x;
    if (bid == 0 && tid == 0) { g_cnt = 0; g_gen = 0; }
    if (bid < NB_A) {
        int i = bid * 256 + tid;
        splitw(A[i], &g_A0h[i], &g_A0l[i]);
    } else {
        int i = (bid - NB_A) * 256 + tid;
        if (i >= LP * H_) return;
        int l = i >> 9, h = i & 511;
        float acc = 0.f;
        if (l < 128) { for (int m = 0; m < M_IN; m++) acc += We[l * M_IN + m] * Wb[m * H_ + h]; }
        else if (l == 128) { for (int m = 0; m < M_IN; m++) acc += be[m] * Wb[m * H_ + h]; }
        splitw(acc, &g_Uh[i], &g_Ul[i]);
    }
}

// ---------------------------------------------------------------------------
__device__ __forceinline__ void ldsm4(uint32_t* r, const void* p) {
    uint32_t addr = (uint32_t)__cvta_generic_to_shared(p);
    asm volatile("ldmatrix.sync.aligned.m8n8.x4.shared.b16 {%0,%1,%2,%3}, [%4];"
                 : "=r"(r[0]), "=r"(r[1]), "=r"(r[2]), "=r"(r[3]) : "r"(addr));
}
__device__ __forceinline__ void ldsm4t(uint32_t* r, const void* p) {
    uint32_t addr = (uint32_t)__cvta_generic_to_shared(p);
    asm volatile("ldmatrix.sync.aligned.m8n8.x4.trans.shared.b16 {%0,%1,%2,%3}, [%4];"
                 : "=r"(r[0]), "=r"(r[1]), "=r"(r[2]), "=r"(r[3]) : "r"(addr));
}
__device__ __forceinline__ void mma16816(float* d, const uint32_t* a, const uint32_t* b) {
    asm volatile("mma.sync.aligned.m16n8k16.row.col.f32.bf16.bf16.f32 "
                 "{%0,%1,%2,%3}, {%4,%5,%6,%7}, {%8,%9}, {%0,%1,%2,%3};"
                 : "+f"(d[0]), "+f"(d[1]), "+f"(d[2]), "+f"(d[3])
                 : "r"(a[0]), "r"(a[1]), "r"(a[2]), "r"(a[3]), "r"(b[0]), "r"(b[1]));
}

// grid-wide barrier (all GRID blocks must be resident)
__device__ __forceinline__ void gbar(int& epoch) {
    __syncthreads();
    __threadfence();
    if (threadIdx.x == 0) {
        int t = atomicAdd(&g_cnt, 1);
        if (t == GRID - 1) {
            atomicExch(&g_cnt, 0);
            __threadfence();
            atomicAdd(&g_gen, 1);
        }
        while (*(volatile int*)&g_gen < epoch + 1) {}
    }
    __syncthreads();
    epoch++;
}

// ---------------------------------------------------------------------------
// shared 64x64 double-buffered split-bf16 mma mainloop, k-chunk 64.
// A chunk ptrs (nullptr = zero rows) point at k-offset 0 of their row (+c8).
// B addressed by row index: row = remap ? (kg>>7)*130+(kg&127) : kg.
__device__ __forceinline__ void coreK(
    const bf16* aH0, const bf16* aL0,
    const bf16* aH1, const bf16* aL1,
    const bf16* __restrict__ bHb, const bf16* __restrict__ bLb, int bcol,
    int k0, int iters, bool remap,
    float acc[2][2][4], char* smx)
{
    bf16* ash = (bf16*)smx;          // [2][64*72]
    bf16* asl = ash + 9216;
    bf16* bsh = asl + 9216;
    bf16* bsl = bsh + 9216;
    int tid = threadIdx.x;
    int lane = tid & 31, wid = tid >> 5;
    int wm = wid & 1, wn = wid >> 1;
    int a_r = (lane & 7) + (lane & 8);
    int a_c = (lane & 16) ? 8 : 0;
    int m0 = tid >> 3;               // chunk0 smem row; chunk1 = +32
    int c8 = (tid & 7) * 8;

    uint4 pA0h = make_uint4(0,0,0,0), pA0l = pA0h, pA1h = pA0h, pA1l = pA0h;
    uint4 pB0h, pB0l, pB1h, pB1l;
    if (aH0) { pA0h = *(const uint4*)aH0; pA0l = *(const uint4*)aL0; }
    if (aH1) { pA1h = *(const uint4*)aH1; pA1l = *(const uint4*)aL1; }
    {
        int kg0 = k0 + m0, kg1 = kg0 + 32;
        int r0 = remap ? ((kg0 >> 7) * LP + (kg0 & 127)) : kg0;
        int r1 = remap ? ((kg1 >> 7) * LP + (kg1 & 127)) : kg1;
        pB0h = *(const uint4*)(bHb + (size_t)r0 * H_ + bcol);
        pB0l = *(const uint4*)(bLb + (size_t)r0 * H_ + bcol);
        pB1h = *(const uint4*)(bHb + (size_t)r1 * H_ + bcol);
        pB1l = *(const uint4*)(bLb + (size_t)r1 * H_ + bcol);
    }

    int st = 0;
    #pragma unroll 1
    for (int it = 0; it < iters; it++) {
        int sb = st * 4608;
        *(uint4*)&ash[sb + m0 * 72 + c8] = pA0h;
        *(uint4*)&asl[sb + m0 * 72 + c8] = pA0l;
        *(uint4*)&ash[sb + (m0 + 32) * 72 + c8] = pA1h;
        *(uint4*)&asl[sb + (m0 + 32) * 72 + c8] = pA1l;
        *(uint4*)&bsh[sb + m0 * 72 + c8] = pB0h;
        *(uint4*)&bsl[sb + m0 * 72 + c8] = pB0l;
        *(uint4*)&bsh[sb + (m0 + 32) * 72 + c8] = pB1h;
        *(uint4*)&bsl[sb + (m0 + 32) * 72 + c8] = pB1l;
        __syncthreads();

        if (it + 1 < iters) {
            int kn = (it + 1) << 6;
            if (aH0) { pA0h = *(const uint4*)(aH0 + kn); pA0l = *(const uint4*)(aL0 + kn); }
            if (aH1) { pA1h = *(const uint4*)(aH1 + kn); pA1l = *(const uint4*)(aL1 + kn); }
            int kg0 = k0 + kn + m0, kg1 = kg0 + 32;
            int r0 = remap ? ((kg0 >> 7) * LP + (kg0 & 127)) : kg0;
            int r1 = remap ? ((kg1 >> 7) * LP + (kg1 & 127)) : kg1;
            pB0h = *(const uint4*)(bHb + (size_t)r0 * H_ + bcol);
            pB0l = *(const uint4*)(bLb + (size_t)r0 * H_ + bcol);
            pB1h = *(const uint4*)(bHb + (size_t)r1 * H_ + bcol);
            pB1l = *(const uint4*)(bLb + (size_t)r1 * H_ + bcol);
        }

        #pragma unroll
        for (int ks = 0; ks < 4; ks++) {
            int kc = ks * 16;
            uint32_t ah[2][4], al[2][4], bh[4], bl[4];
            #pragma unroll
            for (int mt = 0; mt < 2; mt++) {
                int mr = wm * 32 + mt * 16 + a_r;
                ldsm4(ah[mt], &ash[sb + mr * 72 + kc + a_c]);
                ldsm4(al[mt], &asl[sb + mr * 72 + kc + a_c]);
            }
            {
                int nb = wn * 16 + a_c;
                ldsm4t(bh, &bsh[sb + (kc + a_r) * 72 + nb]);
                ldsm4t(bl, &bsl[sb + (kc + a_r) * 72 + nb]);
            }
            #pragma unroll
            for (int mt = 0; mt < 2; mt++)
                #pragma unroll
                for (int nt = 0; nt < 2; nt++) {
                    const uint32_t* bhf = &bh[nt * 2];
                    const uint32_t* blf = &bl[nt * 2];
                    mma16816(acc[mt][nt], ah[mt], bhf);
                    mma16816(acc[mt][nt], ah[mt], blf);
                    mma16816(acc[mt][nt], al[mt], bhf);
                }
        }
        st ^= 1;
    }
    __syncthreads();   // protect smem before next tile reuses it
}

// stage tile: C = [U(:Mu) ; A2] @ A2; outputs hi/lo split rows
__device__ void tg_tile(const bf16* __restrict__ A2h, const bf16* __restrict__ A2l,
                        int Mu, int Mtot,
                        bf16* C1h, bf16* C1l, bf16* C2h, bf16* C2l,
                        int tile, char* smx)
{
    int tid = threadIdx.x;
    int lane = tid & 31, wid = tid >> 5;
    int wm = wid & 1, wn = wid >> 1;
    int row0 = (tile >> 3) * 64, col0 = (tile & 7) * 64;
    int c8 = (tid & 7) * 8;

    const bf16 *aH[2], *aL[2];
    #pragma unroll
    for (int p = 0; p < 2; p++) {
        int m = row0 + (tid >> 3) + p * 32;
        bool ok = (m < Mtot);
        bool lo = ok && (m < Mu);
        aH[p] = ok ? ((lo ? g_Uh : A2h) + (size_t)(lo ? m : m - Mu) * H_ + c8) : nullptr;
        aL[p] = ok ? ((lo ? g_Ul : A2l) + (size_t)(lo ? m : m - Mu) * H_ + c8) : nullptr;
    }

    float acc[2][2][4] = {};
    coreK(aH[0], aL[0], aH[1], aL[1], A2h, A2l, col0 + c8, 0, 8, false, acc, smx);

    #pragma unroll
    for (int mt = 0; mt < 2; mt++)
        #pragma unroll
        for (int nt = 0; nt < 2; nt++) {
            int c = col0 + wn * 16 + nt * 8 + (lane & 3) * 2;
            #pragma unroll
            for (int half = 0; half < 2; half++) {
                int r = row0 + wm * 32 + mt * 16 + (lane >> 2) + half * 8;
                if (r >= Mtot) continue;
                float v0 = acc[mt][nt][half * 2], v1 = acc[mt][nt][half * 2 + 1];
                bool lo = (r < Mu);
                size_t ro = lo ? (size_t)r * H_ : (size_t)(r - Mu) * H_;
                bf16* ch = lo ? C1h : C2h;
                bf16* cl = lo ? C1l : C2l;
                splitw(v0, &ch[ro + c], &cl[ro + c]);
                splitw(v1, &ch[ro + c + 1], &cl[ro + c + 1]);
            }
        }
}

// squaring tile: Gout = Gin @ Gin (64 tiles, M=512)
__device__ void sq_tile(const bf16* __restrict__ Gh, const bf16* __restrict__ Gl,
                        bf16* OutH, bf16* OutL, int tile, char* smx)
{
    int tid = threadIdx.x;
    int lane = tid & 31, wid = tid >> 5;
    int wm = wid & 1, wn = wid >> 1;
    int row0 = (tile >> 3) * 64, col0 = (tile & 7) * 64;
    int c8 = (tid & 7) * 8;
    int m0 = row0 + (tid >> 3);

    float acc[2][2][4] = {};
    coreK(Gh + (size_t)m0 * H_ + c8, Gl + (size_t)m0 * H_ + c8,
          Gh + (size_t)(m0 + 32) * H_ + c8, Gl + (size_t)(m0 + 32) * H_ + c8,
          Gh, Gl, col0 + c8, 0, 8, false, acc, smx);

    #pragma unroll
    for (int mt = 0; mt < 2; mt++)
        #pragma unroll
        for (int nt = 0; nt < 2; nt++) {
            int c = col0 + wn * 16 + nt * 8 + (lane & 3) * 2;
            #pragma unroll
            for (int half = 0; half < 2; half++) {
                int r = row0 + wm * 32 + mt * 16 + (lane >> 2) + half * 8;
                size_t ro = (size_t)r * H_;
                splitw(acc[mt][nt][half * 2],     &OutH[ro + c],     &OutL[ro + c]);
                splitw(acc[mt][nt][half * 2 + 1], &OutH[ro + c + 1], &OutL[ro + c + 1]);
            }
        }
}

// combine tile: out_j = in_{2j} + in_{2j+1} @ G   (stacked: out row m=j*16+b)
__device__ void cb_tile(const float* __restrict__ inF,
                        const bf16* __restrict__ inH, const bf16* __restrict__ inL,
                        const bf16* __restrict__ Gh, const bf16* __restrict__ Gl,
                        float* outF, bf16* outH, bf16* outL,
                        int Mout, int tile, char* smx)
{
    int tid = threadIdx.x;
    int lane = tid & 31, wid = tid >> 5;
    int wm = wid & 1, wn = wid >> 1;
    int row0 = (tile >> 3) * 64, col0 = (tile & 7) * 64;
    int c8 = (tid & 7) * 8;

    const bf16 *aH[2], *aL[2];
    #pragma unroll
    for (int p = 0; p < 2; p++) {
        int m = row0 + (tid >> 3) + p * 32;
        bool ok = (m < Mout);
        int arow = 32 * (m >> 4) + 16 + (m & 15);
        aH[p] = ok ? inH + (size_t)arow * H_ + c8 : nullptr;
        aL[p] = ok ? inL + (size_t)arow * H_ + c8 : nullptr;
    }

    float acc[2][2][4] = {};
    coreK(aH[0], aL[0], aH[1], aL[1], Gh, Gl, col0 + c8, 0, 8, false, acc, smx);

    #pragma unroll
    for (int mt = 0; mt < 2; mt++)
        #pragma unroll
        for (int nt = 0; nt < 2; nt++) {
            int c = col0 + wn * 16 + nt * 8 + (lane & 3) * 2;
            #pragma unroll
            for (int half = 0; half < 2; half++) {
                int r = row0 + wm * 32 + mt * 16 + (lane >> 2) + half * 8;
                if (r >= Mout) continue;
                int ev = 32 * (r >> 4) + (r & 15);
                float v0 = acc[mt][nt][half * 2]     + inF[(size_t)ev * H_ + c];
                float v1 = acc[mt][nt][half * 2 + 1] + inF[(size_t)ev * H_ + c + 1];
                size_t ro = (size_t)r * H_;
                outF[ro + c] = v0;
                outF[ro + c + 1] = v1;
                splitw(v0, &outH[ro + c], &outL[ro + c]);
                splitw(v1, &outH[ro + c + 1], &outL[ro + c + 1]);
            }
        }
}

// zgemm tile: Zp[bz] = X @ U' (U' row k = U row (k>>7)*130+(k&127)), K-slice
__device__ void z_tile(int tile, char* smx) {
    int tid = threadIdx.x;
    int lane = tid & 31, wid = tid >> 5;
    int wm = wid & 1, wn = wid >> 1;
    int bx = tile & 7, by = (tile >> 3) & 3, bz = tile >> 5;
    int row0 = by * 64, col0 = bx * 64;
    int k0 = bz * KPER;
    size_t coff = (size_t)bz * MZ * H_;
    int c8 = (tid & 7) * 8;
    int m0 = row0 + (tid >> 3);

    float acc[2][2][4] = {};
    coreK(g_Xh + (size_t)m0 * KX + k0 + c8, g_Xl + (size_t)m0 * KX + k0 + c8,
          g_Xh + (size_t)(m0 + 32) * KX + k0 + c8, g_Xl + (size_t)(m0 + 32) * KX + k0 + c8,
          g_Uh, g_Ul, col0 + c8, k0, 4, true, acc, smx);

    #pragma unroll
    for (int mt = 0; mt < 2; mt++)
        #pragma unroll
        for (int nt = 0; nt < 2; nt++) {
            int c = col0 + wn * 16 + nt * 8 + (lane & 3) * 2;
            #pragma unroll
            for (int half = 0; half < 2; half++) {
                int r = row0 + wm * 32 + mt * 16 + (lane >> 2) + half * 8;
                float* cp = g_Zp + coff + (size_t)r * H_ + c;
                cp[0] = acc[mt][nt][half * 2];
                cp[1] = acc[mt][nt][half * 2 + 1];
            }
        }
}

// ------------------------------- mega kernel -------------------------------
__global__ __launch_bounds__(256, 2) void k_mega(
    const float* __restrict__ x,
    const float* __restrict__ Wr, const float* __restrict__ br,
    const float* __restrict__ lng, const float* __restrict__ lnb,
    const float* __restrict__ W1, const float* __restrict__ b1,
    const float* __restrict__ W2, const float* __restrict__ b2,
    float* __restrict__ out)
{
    extern __shared__ __align__(16) char smx[];
    int bid = blockIdx.x, tid = threadIdx.x;
    int epoch = 0;

    bf16* P3h = g_Ph + 3 * (size_t)HH; bf16* P3l = g_Pl + 3 * (size_t)HH;  // A^16
    bf16* P4h = g_Ph + 4 * (size_t)HH; bf16* P4l = g_Pl + 4 * (size_t)HH;  // A^32
    bf16* P5h = g_Ph + 5 * (size_t)HH; bf16* P5l = g_Pl + 5 * (size_t)HH;  // A^64
    bf16* P6h = g_Ph + 6 * (size_t)HH; bf16* P6l = g_Pl + 6 * (size_t)HH;  // A^128

    // ---- phase 0: gather X + stage 0..3 (4 gbars) ----
    for (int i = bid * 256 + tid; i < MZ * KX; i += GRID * 256) {
        int m = i >> 11, kk = i & 2047;
        int r = kk >> 7, l = kk & 127;
        int q = m >> 4, b = m & 15;
        float v = x[((size_t)b * T_ + (T_ - 1) - (q * C_CHUNK + r)) * L_ + l];
        splitw(v, &g_Xh[i], &g_Xl[i]);
    }
    {
        const int MuT[4] = {130, 260, 520, 1040};
        const int NTT[4] = {88, 104, 136, 200};
        for (int s = 0; s < 4; s++) {
            const bf16* A2h = s ? g_Ph + (size_t)(s - 1) * HH : g_A0h;
            const bf16* A2l = s ? g_Pl + (size_t)(s - 1) * HH : g_A0l;
            int Mu = MuT[s];
            for (int t = bid; t < NTT[s]; t += GRID)
                tg_tile(A2h, A2l, Mu, Mu + H_,
                        g_Uh + (size_t)Mu * H_, g_Ul + (size_t)Mu * H_,
                        g_Ph + (size_t)s * HH, g_Pl + (size_t)s * HH, t, smx);
            gbar(epoch);
        }
    }

    // ---- phase Z: zgemm (256 tiles) + G1=A^32 squaring (64 tiles) + bias ----
    if (bid * 256 + tid < H_) {
        int h = bid * 256 + tid;
        float s = 0.f;
        #pragma unroll
        for (int r = 0; r < C_CHUNK; r++) {
            size_t off = (size_t)(r * LP + 128) * H_ + h;
            s += __bfloat162float(g_Uh[off]) + __bfloat162float(g_Ul[off]);
        }
        g_bias[h] = s;
    }
    for (int t = bid; t < 256 + 64; t += GRID) {
        if (t < 256) z_tile(t, smx);
        else sq_tile(P3h, P3l, P4h, P4l, t - 256, smx);
    }
    gbar(epoch);

    // ---- phase R: reduce Z (+bias, split) + G2=A^64 squaring ----
    for (int i = bid * 256 + tid; i < MZ * H_; i += GRID * 256) {
        float v = g_bias[i & 511];
        #pragma unroll
        for (int s = 0; s < NSPLIT; s++) v += g_Zp[(size_t)s * (MZ * H_) + i];
        g_Zf[i] = v;
        splitw(v, &g_Zh[i], &g_Zl[i]);
    }
    for (int t = bid; t < 64; t += GRID)
        sq_tile(P4h, P4l, P5h, P5l, t, smx);
    gbar(epoch);

    // ---- level 0: S = Z_even + Z_odd@A^16 (16 tiles) + G3=A^128 squaring ----
    for (int t = bid; t < 16 + 64; t += GRID) {
        if (t < 16) cb_tile(g_Zf, g_Zh, g_Zl, P3h, P3l, g_Waf, g_Wah, g_Wal, 128, t, smx);
        else sq_tile(P5h, P5l, P6h, P6l, t - 16, smx);
    }
    gbar(epoch);

    // ---- level 1: Wa(128) -> Wb(64) with A^32 ----
    for (int t = bid; t < 8; t += GRID)
        cb_tile(g_Waf, g_Wah, g_Wal, P4h, P4l, g_Wbf, g_Wbh, g_Wbl, 64, t, smx);
    gbar(epoch);

    // ---- level 2: Wb(64) -> Wa(32) with A^64 ----
    for (int t = bid; t < 8; t += GRID)
        cb_tile(g_Wbf, g_Wbh, g_Wbl, P5h, P5l, g_Waf, g_Wah, g_Wal, 32, t, smx);
    gbar(epoch);

    // ---- level 3: Wa(32) -> Wb(16) with A^128 : final h_T ----
    for (int t = bid; t < 8; t += GRID)
        cb_tile(g_Waf, g_Wah, g_Wal, P6h, P6l, g_Wbf, g_Wbh, g_Wbl, 16, t, smx);
    gbar(epoch);

    // ---- final: LN + MLP (bid < 16) ----
    if (bid < B_) {
        float* xs = (float*)smx;     // [128]
        float* z  = xs + 128;        // [512]
        float* a  = z + 512;         // [1024]
        float* r1 = a + 1024;        // [8]
        float* r2 = r1 + 8;          // [8]
        float* mus = r2 + 8;         // [2]
        int b = bid;
        if (tid < L_) xs[tid] = x[((size_t)b * T_ + (T_ - 1)) * L_ + tid];
        __syncthreads();
        for (int h = tid; h < H_; h += 256) {
            float acc = g_Wbf[b * H_ + h] + br[h];
            for (int l = 0; l < L_; l++) acc += xs[l] * Wr[(size_t)l * H_ + h];
            z[h] = acc;
        }
        __syncthreads();
        float s1 = 0.f, s2 = 0.f;
        for (int h = tid; h < H_; h += 256) { float v = z[h]; s1 += v; s2 += v * v; }
        #pragma unroll
        for (int o = 16; o; o >>= 1) {
            s1 += __shfl_xor_sync(0xFFFFFFFFu, s1, o);
            s2 += __shfl_xor_sync(0xFFFFFFFFu, s2, o);
        }
        if ((tid & 31) == 0) { r1[tid >> 5] = s1; r2[tid >> 5] = s2; }
        __syncthreads();
        if (tid == 0) {
            float t1 = 0.f, t2 = 0.f;
            #pragma unroll
            for (int i = 0; i < 8; i++) { t1 += r1[i]; t2 += r2[i]; }
            float mu = t1 / (float)H_;
            mus[0] = mu;
            mus[1] = rsqrtf(t2 / (float)H_ - mu * mu + 1e-5f);
        }
        __syncthreads();
        for (int h = tid; h < H_; h += 256) z[h] = (z[h] - mus[0]) * mus[1] * lng[h] + lnb[h];
        __syncthreads();
        for (int f = tid; f < F_; f += 256) {
            float acc = b1[f];
            for (int h = 0; h < H_; h++) acc += z[h] * W1[(size_t)h * F_ + f];
            a[f] = fmaxf(acc, 0.f);
        }
        __syncthreads();
        for (int h2 = tid; h2 < H_; h2 += 256) {
            float acc = b2[h2];
            for (int f = 0; f < F_; f++) acc += a[f] * W2[(size_t)f * H_ + h2];
            out[b * H_ + h2] = acc;
        }
    }
}

// ---------------------------------------------------------------------------
extern "C" void kernel_launch(void* const* d_in, const int* in_sizes, int n_in,
                              void* d_out, int out_size) {
    const float* x   = (const float*)d_in[0];
    const float* We  = (const float*)d_in[1];
    const float* be  = (const float*)d_in[2];
    const float* Wb  = (const float*)d_in[3];
    const float* A   = (const float*)d_in[4];
    const float* Wr  = (const float*)d_in[5];
    const float* br  = (const float*)d_in[6];
    const float* lng = (const float*)d_in[7];
    const float* lnb = (const float*)d_in[8];
    const float* W1  = (const float*)d_in[9];
    const float* b1  = (const float*)d_in[10];
    const float* W2  = (const float*)d_in[11];
    const float* b2  = (const float*)d_in[12];
    float* out = (float*)d_out;

    cudaFuncSetAttribute(k_mega, cudaFuncAttributeMaxDynamicSharedMemorySize,
                         SMEM_BYTES);

    k_prep<<<1024 + 260, 256>>>(A, We, be, Wb);
    k_mega<<<GRID, 256, SMEM_BYTES>>>(x, Wr, br, lng, lnb, W1, b1, W2, b2, out);
}